// round 5
// baseline (speedup 1.0000x reference)
#include <cuda_runtime.h>

#define THREADS 224   // 7 warps: 196 patch threads + slack
#define NWARPS 7

// ---- 4-qubit gate helpers. mask = 8>>q (qubit 0 is MSB of the 4-bit index).
// All called from fully-unrolled loops so mask is a compile-time constant.

__device__ __forceinline__ void apply_rx(float* re, float* im, int mask, float c, float s) {
    // [[c, -i s], [-i s, c]]
#pragma unroll
    for (int i = 0; i < 16; i++) {
        if (i & mask) continue;
        int j = i | mask;
        float r0 = re[i], i0 = im[i], r1 = re[j], i1 = im[j];
        re[i] =  c * r0 + s * i1;
        im[i] =  c * i0 - s * r1;
        re[j] =  s * i0 + c * r1;
        im[j] = -s * r0 + c * i1;
    }
}

__device__ __forceinline__ void apply_ry(float* re, float* im, int mask, float c, float s) {
    // [[c, -s], [s, c]] (real)
#pragma unroll
    for (int i = 0; i < 16; i++) {
        if (i & mask) continue;
        int j = i | mask;
        float r0 = re[i], i0 = im[i], r1 = re[j], i1 = im[j];
        re[i] = c * r0 - s * r1;
        im[i] = c * i0 - s * i1;
        re[j] = s * r0 + c * r1;
        im[j] = s * i0 + c * i1;
    }
}

__device__ __forceinline__ void apply_rz(float* re, float* im, int mask, float c, float s) {
    // diag(c - i s, c + i s)
#pragma unroll
    for (int i = 0; i < 16; i++) {
        if (i & mask) continue;
        int j = i | mask;
        float r0 = re[i], i0 = im[i], r1 = re[j], i1 = im[j];
        re[i] = c * r0 + s * i0;
        im[i] = c * i0 - s * r0;
        re[j] = c * r1 - s * i1;
        im[j] = c * i1 + s * r1;
    }
}

__device__ __forceinline__ void apply_cnot(float* re, float* im, int mc, int mt) {
#pragma unroll
    for (int i = 0; i < 16; i++) {
        if ((i & mc) && !(i & mt)) {
            int j = i | mt;
            float tr = re[i]; re[i] = re[j]; re[j] = tr;
            float ti = im[i]; im[i] = im[j]; im[j] = ti;
        }
    }
}

__global__ __launch_bounds__(THREADS, 4)
void qnet_kernel(const float* __restrict__ x,       // [B,1,28,28]
                 const float* __restrict__ weight,  // [60]
                 const float* __restrict__ fc1_w,   // [64,784]
                 const float* __restrict__ fc1_b,   // [64]
                 const float* __restrict__ fc2_w,   // [10,64]
                 const float* __restrict__ fc2_b,   // [10]
                 float* __restrict__ out)           // [B,10]
{
    __shared__ float  feat[784];    // [patch*4 + q]
    __shared__ float  hidden[64];
    __shared__ float2 cs[60];       // (cos(w/2), sin(w/2)) per weight

    const int b   = blockIdx.x;
    const int tid = threadIdx.x;

    if (tid < 60) {
        float s, c;
        sincosf(weight[tid] * 0.5f, &s, &c);
        cs[tid] = make_float2(c, s);
    }
    __syncthreads();

    if (tid < 196) {
        const int pi = tid / 14, pj = tid % 14;
        const float* xb = x + b * 784 + (2 * pi) * 28 + 2 * pj;
        float ang[4];
        ang[0] = xb[0];  ang[1] = xb[1];
        ang[2] = xb[28]; ang[3] = xb[29];

        float re[16], im[16];
#pragma unroll
        for (int k = 0; k < 16; k++) { re[k] = 0.f; im[k] = 0.f; }
        re[0] = 1.f;

        // Rx encoding: angle = 2*pi*x -> half-angle = pi*x
        const float PI = 3.14159265358979323846f;
#pragma unroll
        for (int q = 0; q < 4; q++) {
            float s, c;
            sincosf(PI * ang[q], &s, &c);
            apply_rx(re, im, 8 >> q, c, s);
        }

        // 5 layers of (Ry, Rz, Ry) + ring CNOTs between layers
#pragma unroll
        for (int layer = 0; layer < 5; layer++) {
            const int base = layer * 12;
#pragma unroll
            for (int q = 0; q < 4; q++) {
                float2 g = cs[base + q];
                apply_ry(re, im, 8 >> q, g.x, g.y);
            }
#pragma unroll
            for (int q = 0; q < 4; q++) {
                float2 g = cs[base + 4 + q];
                apply_rz(re, im, 8 >> q, g.x, g.y);
            }
#pragma unroll
            for (int q = 0; q < 4; q++) {
                float2 g = cs[base + 8 + q];
                apply_ry(re, im, 8 >> q, g.x, g.y);
            }
            if (layer < 4) {
                apply_cnot(re, im, 8, 4);  // CNOT(0,1)
                apply_cnot(re, im, 4, 2);  // CNOT(1,2)
                apply_cnot(re, im, 2, 1);  // CNOT(2,3)
                apply_cnot(re, im, 1, 8);  // CNOT(3,0)
            }
        }

        // <Z_q> expectations
        float e0 = 0.f, e1 = 0.f, e2 = 0.f, e3 = 0.f;
#pragma unroll
        for (int k = 0; k < 16; k++) {
            float p = re[k] * re[k] + im[k] * im[k];
            e0 += (k & 8) ? -p : p;
            e1 += (k & 4) ? -p : p;
            e2 += (k & 2) ? -p : p;
            e3 += (k & 1) ? -p : p;
        }
        feat[tid * 4 + 0] = e0;
        feat[tid * 4 + 1] = e1;
        feat[tid * 4 + 2] = e2;
        feat[tid * 4 + 3] = e3;
    }
    __syncthreads();

    // ---- FC1: hidden[h] = relu(feat . fc1_w[h,:] + fc1_b[h])
    // One hidden unit per warp iteration; lanes read consecutive float4s (coalesced).
    {
        const int warp = tid >> 5;
        const int lane = tid & 31;
        const float4* W4 = reinterpret_cast<const float4*>(fc1_w);
        const float4* F4 = reinterpret_cast<const float4*>(feat);
        for (int h = warp; h < 64; h += NWARPS) {
            float acc = 0.f;
            for (int kk = lane; kk < 196; kk += 32) {
                float4 w = W4[h * 196 + kk];
                float4 f = F4[kk];
                acc += w.x * f.x + w.y * f.y + w.z * f.z + w.w * f.w;
            }
#pragma unroll
            for (int off = 16; off; off >>= 1)
                acc += __shfl_down_sync(0xffffffffu, acc, off);
            if (lane == 0)
                hidden[h] = fmaxf(acc + fc1_b[h], 0.f);
        }
    }
    __syncthreads();

    // ---- FC2: out[b, o] = hidden . fc2_w[o,:] + fc2_b[o]
    if (tid < 10) {
        float acc = fc2_b[tid];
#pragma unroll 8
        for (int h = 0; h < 64; h++)
            acc += hidden[h] * fc2_w[tid * 64 + h];
        out[b * 10 + tid] = acc;
    }
}

extern "C" void kernel_launch(void* const* d_in, const int* in_sizes, int n_in,
                              void* d_out, int out_size) {
    const float* x     = (const float*)d_in[0];
    const float* w     = (const float*)d_in[1];
    const float* fc1_w = (const float*)d_in[2];
    const float* fc1_b = (const float*)d_in[3];
    const float* fc2_w = (const float*)d_in[4];
    const float* fc2_b = (const float*)d_in[5];
    float* out = (float*)d_out;

    const int B = in_sizes[0] / 784;  // 128
    qnet_kernel<<<B, THREADS>>>(x, w, fc1_w, fc1_b, fc2_w, fc2_b, out);
}